// round 12
// baseline (speedup 1.0000x reference)
#include <cuda_runtime.h>
#include <cuda_fp16.h>
#include <cstdint>

// ---------------------------------------------------------------------------
// Self-attention, sm_103 baseline ISA. Round 12: fp16 single-product GEMMs
// (numerics frozen since R7; rel_err must stay bit-exact 0.0008065866).
// Diagnosis R7-R11: LDSM crossbar time (~384 cyc/k-step/SMSP) ~= HMMA pipe
// time, but the chunk-barrier phase convoy makes them ALTERNATE (tensor
// ~44%). Fix within the 128-reg budget: pair-structured inner loop --
// bf pre-loaded for 2 k-steps (16 regs), af WAR-recycled in place between
// the two MMA batches, so LDSM overlaps the tensor pipe drain.
// Base config unchanged from R11: 512-thr CTA, tile 128x256, warp 64x32,
// 3-stage cp.async, wait_group(1).
// ---------------------------------------------------------------------------

#define BMT 128
#define BNT 256
#define BKT 64
#define SSTR 144                    // smem row stride bytes (128B data + 16 pad)
#define TILE_A (128 * SSTR)         // 18432 B
#define TILE_BB (256 * SSTR)        // 36864 B
#define STAGE_B (TILE_A + TILE_BB)  // 55296 B
#define SMEM_SZ (3 * STAGE_B)       // 165888 B (3-stage, 1 CTA/SM)

static constexpr long long QKV_ONE = 16384LL * 1024LL;

__device__ __half g_xh[16384LL * 1024];
__device__ __half g_wt[3LL * 1024 * 1024];
__device__ __half g_qkh[2 * 16384LL * 1024];
__device__ __half g_vt[8LL * 1024 * 2048];
__device__ float  g_scores[8LL * 2048 * 2048];
__device__ __half g_ah[8LL * 2048 * 2048];

// ---------------- PTX helpers ----------------
__device__ __forceinline__ uint32_t s2u(const void* p) {
    uint32_t a;
    asm("{ .reg .u64 t; cvta.to.shared.u64 t, %1; cvt.u32.u64 %0, t; }" : "=r"(a) : "l"(p));
    return a;
}
__device__ __forceinline__ void cpasync16(uint32_t d, const void* s) {
    asm volatile("cp.async.cg.shared.global [%0], [%1], 16;" :: "r"(d), "l"(s) : "memory");
}
#define CP_COMMIT() asm volatile("cp.async.commit_group;" ::: "memory")
#define CP_WAIT(n)  asm volatile("cp.async.wait_group %0;" :: "n"(n) : "memory")

__device__ __forceinline__ void ldsm4(uint32_t* r, uint32_t a) {
    asm volatile("ldmatrix.sync.aligned.m8n8.x4.shared.b16 {%0,%1,%2,%3}, [%4];"
                 : "=r"(r[0]), "=r"(r[1]), "=r"(r[2]), "=r"(r[3]) : "r"(a));
}
__device__ __forceinline__ void mma_f16(float* d, const uint32_t* a, const uint32_t* b) {
    asm volatile(
        "mma.sync.aligned.m16n8k16.row.col.f32.f16.f16.f32 "
        "{%0,%1,%2,%3}, {%4,%5,%6,%7}, {%8,%9}, {%0,%1,%2,%3};"
        : "+f"(d[0]), "+f"(d[1]), "+f"(d[2]), "+f"(d[3])
        : "r"(a[0]), "r"(a[1]), "r"(a[2]), "r"(a[3]), "r"(b[0]), "r"(b[1]));
}

// ---------------- fp16 GEMM: C[M,N] = sum_k A[m][k]*B[n][k] ----------------
template <int OUT>   // 0: fp32 C, 1: fp16 C
__global__ __launch_bounds__(512, 1) void h_gemm(
    const __half* __restrict__ Ag, const __half* __restrict__ Bg,
    float* __restrict__ Cf, __half* __restrict__ Ch,
    int K, int lda, int ldb, int ldc,
    long long batA, long long batB, long long batC)
{
    extern __shared__ char smem[];
    const uint32_t sb = s2u(smem);
    const int tid = threadIdx.x;
    const int lane = tid & 31, warp = tid >> 5;
    const int wM = warp & 1;        // 2 warps along M (64 rows each)
    const int wN = warp >> 1;       // 8 warps along N (32 cols each)
    const int lm = lane >> 3, lr = lane & 7;
    const int gid = lane >> 2, tig = lane & 3;

    const long long rowBase = (long long)blockIdx.y * BMT;
    const long long colBase = (long long)blockIdx.x * BNT;
    const char* A = (const char*)(Ag + blockIdx.z * batA);
    const char* B = (const char*)(Bg + blockIdx.z * batB);

    // ldmatrix lane base addresses (add stage offset + k-offset bytes)
    const uint32_t aBase = (uint32_t)(wM * 64 + (lm & 1) * 8 + lr) * SSTR + ((lm >> 1) * 8) * 2;
    const uint32_t bBase = TILE_A + (uint32_t)(wN * 32 + (lm >> 1) * 8 + lr) * SSTR + ((lm & 1) * 8) * 2;

    // cp.async coordinates
    const int ldrA = tid >> 2;           // A row 0..127
    const int cbA  = (tid & 3) * 32;     // 0/32/64/96 within 128B row
    const int ldrB = tid >> 1;           // B row 0..255
    const int cbB  = (tid & 1) * 64;     // 0/64 within 128B row

    float acc[4][4][4];
#pragma unroll
    for (int i = 0; i < 4; i++)
#pragma unroll
        for (int j = 0; j < 4; j++)
#pragma unroll
            for (int c = 0; c < 4; c++) acc[i][j][c] = 0.f;

    const int nCh = K / BKT;

    auto loadA = [&](int c) {
        const uint32_t st = sb + (uint32_t)(c % 3) * STAGE_B;
        const char* g = A + (rowBase + ldrA) * (long long)lda * 2 + (long long)c * (BKT * 2) + cbA;
        const uint32_t t0 = st + ldrA * SSTR + cbA;
        cpasync16(t0, g);
        cpasync16(t0 + 16, g + 16);
    };
    auto loadB = [&](int c) {
        const uint32_t st = sb + (uint32_t)(c % 3) * STAGE_B + TILE_A;
        const char* g = B + (colBase + ldrB) * (long long)ldb * 2 + (long long)c * (BKT * 2) + cbB;
        const uint32_t t0 = st + ldrB * SSTR + cbB;
#pragma unroll
        for (int i = 0; i < 4; i++)
            cpasync16(t0 + i * 16, g + i * 16);
    };

    loadA(0); loadB(0); CP_COMMIT();
    loadA(1); loadB(1); CP_COMMIT();

    for (int c = 0; c < nCh; ++c) {
        if (c + 1 < nCh) { CP_WAIT(1); } else { CP_WAIT(0); }
        __syncthreads();   // stage c visible (landed a chunk ago); safe to refill (c+2)%3

        const uint32_t stg = sb + (uint32_t)(c % 3) * STAGE_B;
        const bool pf = (c + 2 < nCh);

#pragma unroll
        for (int p2 = 0; p2 < 2; p2++) {        // two k-step pairs: ks = 2*p2, 2*p2+1
            uint32_t af[4][4], bfp[2][2][4];
            const uint32_t ko = (uint32_t)p2 * 64;   // 2 k-steps = 64 bytes

            // bf for BOTH k-steps of the pair (stays resident)
#pragma unroll
            for (int s = 0; s < 2; s++)
#pragma unroll
                for (int q = 0; q < 2; q++)
                    ldsm4(bfp[s][q], stg + bBase + q * 16 * SSTR + ko + s * 32);
            // af for step 0
#pragma unroll
            for (int mt = 0; mt < 4; mt++)
                ldsm4(af[mt], stg + aBase + mt * 16 * SSTR + ko);

            if (p2 == 0 && pf) loadA(c + 2);    // global prefetch under compute

            // MMA k-step 2*p2
#pragma unroll
            for (int mt = 0; mt < 4; mt++)
#pragma unroll
                for (int nt = 0; nt < 4; nt++)
                    mma_f16(acc[mt][nt], af[mt], &bfp[0][nt >> 1][(nt & 1) * 2]);

            // af for step 1: WAR-recycle the same registers (MMAs above have
            // issued; LDSM overlaps the tensor-pipe drain)
#pragma unroll
            for (int mt = 0; mt < 4; mt++)
                ldsm4(af[mt], stg + aBase + mt * 16 * SSTR + ko + 32);

            if (p2 == 0 && pf) { loadB(c + 2); CP_COMMIT(); }

            // MMA k-step 2*p2+1
#pragma unroll
            for (int mt = 0; mt < 4; mt++)
#pragma unroll
                for (int nt = 0; nt < 4; nt++)
                    mma_f16(acc[mt][nt], af[mt], &bfp[1][nt >> 1][(nt & 1) * 2]);
        }
    }

    // ---- epilogue ----
#pragma unroll
    for (int mt = 0; mt < 4; mt++) {
        const long long r0 = rowBase + wM * 64 + mt * 16 + gid;
#pragma unroll
        for (int nt = 0; nt < 4; nt++) {
            const long long c0 = colBase + wN * 32 + nt * 8 + tig * 2;
            if (OUT == 1) {
                __half* cp = Ch + blockIdx.z * batC;
                *(__half2*)&cp[r0 * ldc + c0] =
                    __floats2half2_rn(acc[mt][nt][0], acc[mt][nt][1]);
                *(__half2*)&cp[(r0 + 8) * ldc + c0] =
                    __floats2half2_rn(acc[mt][nt][2], acc[mt][nt][3]);
            } else {
                float* cp = Cf + blockIdx.z * batC;
                *(float2*)&cp[r0 * ldc + c0] =
                    make_float2(acc[mt][nt][0], acc[mt][nt][1]);
                *(float2*)&cp[(r0 + 8) * ldc + c0] =
                    make_float2(acc[mt][nt][2], acc[mt][nt][3]);
            }
        }
    }
}

// ---------------- conversion kernels ----------------
__global__ __launch_bounds__(256) void cvt_x(
    const float4* __restrict__ in, __half* __restrict__ out, int n4)
{
    int i = blockIdx.x * 256 + threadIdx.x;
    if (i >= n4) return;
    float4 v = in[i];
    ((__half2*)out)[2 * i]     = __floats2half2_rn(v.x, v.y);
    ((__half2*)out)[2 * i + 1] = __floats2half2_rn(v.z, v.w);
}

// out[z][c][r] = in[z][r][c] as fp16
__global__ __launch_bounds__(256) void transpose_cvt(
    const float* __restrict__ in, __half* __restrict__ out,
    int R, int C, long long batIn, long long batOut)
{
    __shared__ float t[32][33];
    const float* ip = in + blockIdx.z * batIn;
    const long long ob = blockIdx.z * batOut;
    const int c0 = blockIdx.x * 32, r0 = blockIdx.y * 32;
    const int tx = threadIdx.x, ty = threadIdx.y;
#pragma unroll
    for (int i = 0; i < 32; i += 8)
        t[ty + i][tx] = ip[(long long)(r0 + ty + i) * C + c0 + tx];
    __syncthreads();
#pragma unroll
    for (int i = 0; i < 32; i += 8)
        out[ob + (long long)(c0 + ty + i) * R + r0 + tx] = __float2half(t[tx][ty + i]);
}

// softmax over rows of 2048; 1/8 scale folded in; fp16 output
__global__ __launch_bounds__(256) void softmax_h(
    const float* __restrict__ sc, __half* __restrict__ out)
{
    const float SC = 0.125f;
    const long long row = blockIdx.x;
    const float* p = sc + row * 2048;
    const int t = threadIdx.x, lane = t & 31, w = t >> 5;

    float4 v0 = ((const float4*)p)[t];
    float4 v1 = ((const float4*)p)[t + 256];
    float x[8] = {v0.x, v0.y, v0.z, v0.w, v1.x, v1.y, v1.z, v1.w};

    float m = -1e30f;
#pragma unroll
    for (int i = 0; i < 8; i++) { x[i] *= SC; m = fmaxf(m, x[i]); }
#pragma unroll
    for (int o = 16; o > 0; o >>= 1) m = fmaxf(m, __shfl_xor_sync(0xffffffffu, m, o));

    __shared__ float red[8];
    if (lane == 0) red[w] = m;
    __syncthreads();
    float bm = red[0];
#pragma unroll
    for (int i = 1; i < 8; i++) bm = fmaxf(bm, red[i]);

    float s = 0.f;
#pragma unroll
    for (int i = 0; i < 8; i++) { x[i] = expf(x[i] - bm); s += x[i]; }
#pragma unroll
    for (int o = 16; o > 0; o >>= 1) s += __shfl_xor_sync(0xffffffffu, s, o);
    __syncthreads();
    if (lane == 0) red[w] = s;
    __syncthreads();
    float tot = 0.f;
#pragma unroll
    for (int i = 0; i < 8; i++) tot += red[i];
    const float inv = 1.0f / tot;

    __half2* op = (__half2*)(out + row * 2048);
    op[2 * t]       = __floats2half2_rn(x[0] * inv, x[1] * inv);
    op[2 * t + 1]   = __floats2half2_rn(x[2] * inv, x[3] * inv);
    op[2 * t + 512] = __floats2half2_rn(x[4] * inv, x[5] * inv);
    op[2 * t + 513] = __floats2half2_rn(x[6] * inv, x[7] * inv);
}

// ---------------- host ----------------
extern "C" void kernel_launch(void* const* d_in, const int* in_sizes, int n_in,
                              void* d_out, int out_size) {
    const float* x = (const float*)d_in[0];
    const float* w = (const float*)d_in[1];
    float* out = (float*)d_out;

    __half *xh, *wt, *qkh, *vt, *ah;
    float* scores;
    cudaGetSymbolAddress((void**)&xh, g_xh);
    cudaGetSymbolAddress((void**)&wt, g_wt);
    cudaGetSymbolAddress((void**)&qkh, g_qkh);
    cudaGetSymbolAddress((void**)&vt, g_vt);
    cudaGetSymbolAddress((void**)&scores, g_scores);
    cudaGetSymbolAddress((void**)&ah, g_ah);

    cudaFuncSetAttribute(h_gemm<0>, cudaFuncAttributeMaxDynamicSharedMemorySize, SMEM_SZ);
    cudaFuncSetAttribute(h_gemm<1>, cudaFuncAttributeMaxDynamicSharedMemorySize, SMEM_SZ);

    // 1) x -> fp16
    cvt_x<<<16384, 256>>>((const float4*)x, xh, 16384 * 1024 / 4);

    // 2) W transpose -> wt[z][d][h] fp16
    transpose_cvt<<<dim3(32, 32, 3), dim3(32, 8)>>>(
        w, wt, 1024, 1024, 1024LL * 1024, 1024LL * 1024);

    // 3) Q,K projections: [s][d] fp16  (M=16384, N=1024, K=1024; z = Q/K)
    h_gemm<1><<<dim3(4, 128, 2), 512, SMEM_SZ>>>(
        xh, wt, nullptr, qkh,
        1024, 1024, 1024, 1024, 0LL, 1024LL * 1024, QKV_ONE);

    // 4) V projection, produced TRANSPOSED: vt[b][d][s] fp16 (M=1024, N=2048)
    h_gemm<1><<<dim3(8, 8, 8), 512, SMEM_SZ>>>(
        wt + 2LL * 1024 * 1024, xh, nullptr, vt,
        1024, 1024, 1024, 2048, 0LL, 2048LL * 1024, 1024LL * 2048);

    // 5) S = Q @ K^T per batch -> fp32 (M=2048, N=2048, K=1024)
    h_gemm<0><<<dim3(8, 16, 8), 512, SMEM_SZ>>>(
        qkh, qkh + QKV_ONE, scores, nullptr,
        1024, 1024, 1024, 2048, 2048LL * 1024, 2048LL * 1024, 2048LL * 2048);

    // 6) softmax -> fp16 A
    softmax_h<<<16384, 256>>>(scores, ah);

    // 7) out = A @ V per batch (M=2048, N=1024, K=2048); B = vt[d][s] K-major
    h_gemm<0><<<dim3(4, 16, 8), 512, SMEM_SZ>>>(
        ah, vt, out, nullptr,
        2048, 2048, 2048, 1024, 2048LL * 2048, 1024LL * 2048, 2048LL * 1024);
}

// round 14
// speedup vs baseline: 1.0857x; 1.0857x over previous
#include <cuda_runtime.h>
#include <cuda_fp16.h>
#include <cstdint>

// ---------------------------------------------------------------------------
// Self-attention, sm_103 baseline ISA. Round 14: CORRECTED factorization.
//   S = (xWq)(xWk)^T = x (Wq Wk^T) x^T   -- contraction over d, h x h matrix
// R13 contracted over h (wrong index -> rel_err 1.38). Fixed:
//   W''t[h'][h] = sum_d Wk[h'][d] Wq[h][d]   (A=Wk raw, B=Wq raw, 2.1 GF)
//   T[s][h']    = sum_h x[s][h] W''t[h'][h]  (34.4 GF; replaces Q AND K proj)
//   S[q][k]     = sum_h' T[q][h'] x[k][h']   (68.7 GF, reuses xh)
// Quantization-path count into S unchanged (6 eps^2) -> rel_err ~8.1e-4.
// GEMM kernel/config = R11 best (512-thr CTA, 128x256 tile, 64x32 warp tile,
// 3-stage cp.async, wait_group(1)).
// ---------------------------------------------------------------------------

#define BMT 128
#define BNT 256
#define BKT 64
#define SSTR 144                    // smem row stride bytes (128B data + 16 pad)
#define TILE_A (128 * SSTR)         // 18432 B
#define TILE_BB (256 * SSTR)        // 36864 B
#define STAGE_B (TILE_A + TILE_BB)  // 55296 B
#define SMEM_SZ (3 * STAGE_B)       // 165888 B (3-stage, 1 CTA/SM)

__device__ __half g_xh[16384LL * 1024];
__device__ __half g_wh[2LL * 1024 * 1024];    // fp16(kernel[0]), fp16(kernel[1]) raw [h][d]
__device__ __half g_wtv[1024LL * 1024];       // Wv^T  [d][h]
__device__ __half g_wpt[1024LL * 1024];       // W''t = Wk.Wq^T over d, stored [h'][h]
__device__ __half g_t[16384LL * 1024];        // T = x.W''  ([s][h'])
__device__ __half g_vt[8LL * 1024 * 2048];
__device__ float  g_scores[8LL * 2048 * 2048];
__device__ __half g_ah[8LL * 2048 * 2048];

// ---------------- PTX helpers ----------------
__device__ __forceinline__ uint32_t s2u(const void* p) {
    uint32_t a;
    asm("{ .reg .u64 t; cvta.to.shared.u64 t, %1; cvt.u32.u64 %0, t; }" : "=r"(a) : "l"(p));
    return a;
}
__device__ __forceinline__ void cpasync16(uint32_t d, const void* s) {
    asm volatile("cp.async.cg.shared.global [%0], [%1], 16;" :: "r"(d), "l"(s) : "memory");
}
#define CP_COMMIT() asm volatile("cp.async.commit_group;" ::: "memory")
#define CP_WAIT(n)  asm volatile("cp.async.wait_group %0;" :: "n"(n) : "memory")

__device__ __forceinline__ void ldsm4(uint32_t* r, uint32_t a) {
    asm volatile("ldmatrix.sync.aligned.m8n8.x4.shared.b16 {%0,%1,%2,%3}, [%4];"
                 : "=r"(r[0]), "=r"(r[1]), "=r"(r[2]), "=r"(r[3]) : "r"(a));
}
__device__ __forceinline__ void mma_f16(float* d, const uint32_t* a, const uint32_t* b) {
    asm volatile(
        "mma.sync.aligned.m16n8k16.row.col.f32.f16.f16.f32 "
        "{%0,%1,%2,%3}, {%4,%5,%6,%7}, {%8,%9}, {%0,%1,%2,%3};"
        : "+f"(d[0]), "+f"(d[1]), "+f"(d[2]), "+f"(d[3])
        : "r"(a[0]), "r"(a[1]), "r"(a[2]), "r"(a[3]), "r"(b[0]), "r"(b[1]));
}

// ---------------- fp16 GEMM: C[M,N] = sum_k A[m][k]*B[n][k] ----------------
template <int OUT>   // 0: fp32 C, 1: fp16 C
__global__ __launch_bounds__(512, 1) void h_gemm(
    const __half* __restrict__ Ag, const __half* __restrict__ Bg,
    float* __restrict__ Cf, __half* __restrict__ Ch,
    int K, int lda, int ldb, int ldc,
    long long batA, long long batB, long long batC)
{
    extern __shared__ char smem[];
    const uint32_t sb = s2u(smem);
    const int tid = threadIdx.x;
    const int lane = tid & 31, warp = tid >> 5;
    const int wM = warp & 1;        // 2 warps along M (64 rows each)
    const int wN = warp >> 1;       // 8 warps along N (32 cols each)
    const int lm = lane >> 3, lr = lane & 7;
    const int gid = lane >> 2, tig = lane & 3;

    const long long rowBase = (long long)blockIdx.y * BMT;
    const long long colBase = (long long)blockIdx.x * BNT;
    const char* A = (const char*)(Ag + blockIdx.z * batA);
    const char* B = (const char*)(Bg + blockIdx.z * batB);

    const uint32_t aBase = (uint32_t)(wM * 64 + (lm & 1) * 8 + lr) * SSTR + ((lm >> 1) * 8) * 2;
    const uint32_t bBase = TILE_A + (uint32_t)(wN * 32 + (lm >> 1) * 8 + lr) * SSTR + ((lm & 1) * 8) * 2;

    const int ldrA = tid >> 2;           // A row 0..127
    const int cbA  = (tid & 3) * 32;     // 0/32/64/96 within 128B row
    const int ldrB = tid >> 1;           // B row 0..255
    const int cbB  = (tid & 1) * 64;     // 0/64 within 128B row

    float acc[4][4][4];
#pragma unroll
    for (int i = 0; i < 4; i++)
#pragma unroll
        for (int j = 0; j < 4; j++)
#pragma unroll
            for (int c = 0; c < 4; c++) acc[i][j][c] = 0.f;

    const int nCh = K / BKT;

    auto loadA = [&](int c) {
        const uint32_t st = sb + (uint32_t)(c % 3) * STAGE_B;
        const char* g = A + (rowBase + ldrA) * (long long)lda * 2 + (long long)c * (BKT * 2) + cbA;
        const uint32_t t0 = st + ldrA * SSTR + cbA;
        cpasync16(t0, g);
        cpasync16(t0 + 16, g + 16);
    };
    auto loadB = [&](int c) {
        const uint32_t st = sb + (uint32_t)(c % 3) * STAGE_B + TILE_A;
        const char* g = B + (colBase + ldrB) * (long long)ldb * 2 + (long long)c * (BKT * 2) + cbB;
        const uint32_t t0 = st + ldrB * SSTR + cbB;
#pragma unroll
        for (int i = 0; i < 4; i++)
            cpasync16(t0 + i * 16, g + i * 16);
    };

    loadA(0); loadB(0); CP_COMMIT();
    loadA(1); loadB(1); CP_COMMIT();

    for (int c = 0; c < nCh; ++c) {
        if (c + 1 < nCh) { CP_WAIT(1); } else { CP_WAIT(0); }
        __syncthreads();   // stage c visible (landed a chunk ago); safe to refill (c+2)%3

        const uint32_t stg = sb + (uint32_t)(c % 3) * STAGE_B;
        const bool pf = (c + 2 < nCh);

#pragma unroll
        for (int i = 0; i < 4; i++) {           // ks = i*16
            uint32_t af[4][4], bf_[2][4];
            const uint32_t ko = (uint32_t)i * 32;
#pragma unroll
            for (int mt = 0; mt < 4; mt++)
                ldsm4(af[mt], stg + aBase + mt * 16 * SSTR + ko);
#pragma unroll
            for (int p = 0; p < 2; p++)
                ldsm4(bf_[p], stg + bBase + p * 16 * SSTR + ko);

            if (i == 0 && pf) loadA(c + 2);     // prefetch hides under MMAs
            if (i == 1 && pf) { loadB(c + 2); CP_COMMIT(); }

#pragma unroll
            for (int mt = 0; mt < 4; mt++)
#pragma unroll
                for (int nt = 0; nt < 4; nt++)
                    mma_f16(acc[mt][nt], af[mt], &bf_[nt >> 1][(nt & 1) * 2]);
        }
    }

    // ---- epilogue ----
#pragma unroll
    for (int mt = 0; mt < 4; mt++) {
        const long long r0 = rowBase + wM * 64 + mt * 16 + gid;
#pragma unroll
        for (int nt = 0; nt < 4; nt++) {
            const long long c0 = colBase + wN * 32 + nt * 8 + tig * 2;
            if (OUT == 1) {
                __half* cp = Ch + blockIdx.z * batC;
                *(__half2*)&cp[r0 * ldc + c0] =
                    __floats2half2_rn(acc[mt][nt][0], acc[mt][nt][1]);
                *(__half2*)&cp[(r0 + 8) * ldc + c0] =
                    __floats2half2_rn(acc[mt][nt][2], acc[mt][nt][3]);
            } else {
                float* cp = Cf + blockIdx.z * batC;
                *(float2*)&cp[r0 * ldc + c0] =
                    make_float2(acc[mt][nt][0], acc[mt][nt][1]);
                *(float2*)&cp[(r0 + 8) * ldc + c0] =
                    make_float2(acc[mt][nt][2], acc[mt][nt][3]);
            }
        }
    }
}

// ---------------- conversion kernels ----------------
__global__ __launch_bounds__(256) void cvt_f2h(
    const float4* __restrict__ in, __half* __restrict__ out, int n4)
{
    int i = blockIdx.x * 256 + threadIdx.x;
    if (i >= n4) return;
    float4 v = in[i];
    ((__half2*)out)[2 * i]     = __floats2half2_rn(v.x, v.y);
    ((__half2*)out)[2 * i + 1] = __floats2half2_rn(v.z, v.w);
}

// out[z][c][r] = in[z][r][c] as fp16
__global__ __launch_bounds__(256) void transpose_cvt(
    const float* __restrict__ in, __half* __restrict__ out,
    int R, int C, long long batIn, long long batOut)
{
    __shared__ float t[32][33];
    const float* ip = in + blockIdx.z * batIn;
    const long long ob = blockIdx.z * batOut;
    const int c0 = blockIdx.x * 32, r0 = blockIdx.y * 32;
    const int tx = threadIdx.x, ty = threadIdx.y;
#pragma unroll
    for (int i = 0; i < 32; i += 8)
        t[ty + i][tx] = ip[(long long)(r0 + ty + i) * C + c0 + tx];
    __syncthreads();
#pragma unroll
    for (int i = 0; i < 32; i += 8)
        out[ob + (long long)(c0 + ty + i) * R + r0 + tx] = __float2half(t[tx][ty + i]);
}

// softmax over rows of 2048; 1/8 scale folded in; fp16 output
__global__ __launch_bounds__(256) void softmax_h(
    const float* __restrict__ sc, __half* __restrict__ out)
{
    const float SC = 0.125f;
    const long long row = blockIdx.x;
    const float* p = sc + row * 2048;
    const int t = threadIdx.x, lane = t & 31, w = t >> 5;

    float4 v0 = ((const float4*)p)[t];
    float4 v1 = ((const float4*)p)[t + 256];
    float x[8] = {v0.x, v0.y, v0.z, v0.w, v1.x, v1.y, v1.z, v1.w};

    float m = -1e30f;
#pragma unroll
    for (int i = 0; i < 8; i++) { x[i] *= SC; m = fmaxf(m, x[i]); }
#pragma unroll
    for (int o = 16; o > 0; o >>= 1) m = fmaxf(m, __shfl_xor_sync(0xffffffffu, m, o));

    __shared__ float red[8];
    if (lane == 0) red[w] = m;
    __syncthreads();
    float bm = red[0];
#pragma unroll
    for (int i = 1; i < 8; i++) bm = fmaxf(bm, red[i]);

    float s = 0.f;
#pragma unroll
    for (int i = 0; i < 8; i++) { x[i] = expf(x[i] - bm); s += x[i]; }
#pragma unroll
    for (int o = 16; o > 0; o >>= 1) s += __shfl_xor_sync(0xffffffffu, s, o);
    __syncthreads();
    if (lane == 0) red[w] = s;
    __syncthreads();
    float tot = 0.f;
#pragma unroll
    for (int i = 0; i < 8; i++) tot += red[i];
    const float inv = 1.0f / tot;

    __half2* op = (__half2*)(out + row * 2048);
    op[2 * t]       = __floats2half2_rn(x[0] * inv, x[1] * inv);
    op[2 * t + 1]   = __floats2half2_rn(x[2] * inv, x[3] * inv);
    op[2 * t + 512] = __floats2half2_rn(x[4] * inv, x[5] * inv);
    op[2 * t + 513] = __floats2half2_rn(x[6] * inv, x[7] * inv);
}

// ---------------- host ----------------
extern "C" void kernel_launch(void* const* d_in, const int* in_sizes, int n_in,
                              void* d_out, int out_size) {
    const float* x = (const float*)d_in[0];
    const float* w = (const float*)d_in[1];
    float* out = (float*)d_out;

    __half *xh, *wh, *wtv, *wpt, *th, *vt, *ah;
    float* scores;
    cudaGetSymbolAddress((void**)&xh, g_xh);
    cudaGetSymbolAddress((void**)&wh, g_wh);
    cudaGetSymbolAddress((void**)&wtv, g_wtv);
    cudaGetSymbolAddress((void**)&wpt, g_wpt);
    cudaGetSymbolAddress((void**)&th, g_t);
    cudaGetSymbolAddress((void**)&vt, g_vt);
    cudaGetSymbolAddress((void**)&scores, g_scores);
    cudaGetSymbolAddress((void**)&ah, g_ah);

    cudaFuncSetAttribute(h_gemm<0>, cudaFuncAttributeMaxDynamicSharedMemorySize, SMEM_SZ);
    cudaFuncSetAttribute(h_gemm<1>, cudaFuncAttributeMaxDynamicSharedMemorySize, SMEM_SZ);

    // 1) x -> fp16
    cvt_f2h<<<16384, 256>>>((const float4*)x, xh, 16384 * 1024 / 4);

    // 2a) Wq, Wk -> fp16 raw [h][d] (no transpose; K-major over d)
    cvt_f2h<<<2048, 256>>>((const float4*)w, wh, 2 * 1024 * 1024 / 4);

    // 2b) Wv^T -> wtv[d][h] fp16 (for transposed V projection)
    transpose_cvt<<<dim3(32, 32, 1), dim3(32, 8)>>>(
        w + 2LL * 1024 * 1024, wtv, 1024, 1024, 0LL, 0LL);

    // 3) W''t[h'][h] = sum_d Wk[h'][d] * Wq[h][d]   (M=1024, N=1024, K=1024)
    h_gemm<1><<<dim3(4, 8, 1), 512, SMEM_SZ>>>(
        wh + 1024LL * 1024, wh, nullptr, wpt,
        1024, 1024, 1024, 1024, 0LL, 0LL, 0LL);

    // 4) T[s][h'] = sum_h x[s][h] * W''t[h'][h]   (M=16384, N=1024, K=1024)
    h_gemm<1><<<dim3(4, 128, 1), 512, SMEM_SZ>>>(
        xh, wpt, nullptr, th,
        1024, 1024, 1024, 1024, 0LL, 0LL, 0LL);

    // 5) V projection, produced TRANSPOSED: vt[b][d][s] (M=1024, N=2048)
    h_gemm<1><<<dim3(8, 8, 8), 512, SMEM_SZ>>>(
        wtv, xh, nullptr, vt,
        1024, 1024, 1024, 2048, 0LL, 2048LL * 1024, 1024LL * 2048);

    // 6) S[q][k] = sum_h' T[q][h'] * x[k][h'] per batch (M=2048, N=2048)
    h_gemm<0><<<dim3(8, 16, 8), 512, SMEM_SZ>>>(
        th, xh, scores, nullptr,
        1024, 1024, 1024, 2048, 2048LL * 1024, 2048LL * 1024, 2048LL * 2048);

    // 7) softmax -> fp16 A
    softmax_h<<<16384, 256>>>(scores, ah);

    // 8) out = A @ V per batch (M=2048, N=1024, K=2048); B = vt[d][s] K-major
    h_gemm<0><<<dim3(4, 16, 8), 512, SMEM_SZ>>>(
        ah, vt, out, nullptr,
        2048, 2048, 2048, 1024, 2048LL * 2048, 1024LL * 2048, 2048LL * 1024);
}

// round 15
// speedup vs baseline: 1.1790x; 1.0860x over previous
#include <cuda_runtime.h>
#include <cuda_fp16.h>
#include <cstdint>

// ---------------------------------------------------------------------------
// Self-attention, sm_103 baseline ISA. Round 15: R14 algebra (factored
// S = x(WqWk^T)x^T, fp16 single-product GEMMs) + fork/join stream overlap
// inside graph capture:
//   s1: cvt(Wq,Wk) -> Wv^T -> W''   (tiny grid; overlaps cvt_x + V)
//   s2: V-projection                 (overlaps T and S on s0)
//   s0: cvt_x -> T -> S -> softmax -> (join V) -> AV
// Per-kernel numerics identical to R14 -> rel_err must stay 0.0008112911.
// ---------------------------------------------------------------------------

#define BMT 128
#define BNT 256
#define BKT 64
#define SSTR 144                    // smem row stride bytes (128B data + 16 pad)
#define TILE_A (128 * SSTR)         // 18432 B
#define TILE_BB (256 * SSTR)        // 36864 B
#define STAGE_B (TILE_A + TILE_BB)  // 55296 B
#define SMEM_SZ (3 * STAGE_B)       // 165888 B (3-stage, 1 CTA/SM)

__device__ __half g_xh[16384LL * 1024];
__device__ __half g_wh[2LL * 1024 * 1024];    // fp16(Wq), fp16(Wk) raw [h][d]
__device__ __half g_wtv[1024LL * 1024];       // Wv^T  [d][h]
__device__ __half g_wpt[1024LL * 1024];       // W''t = Wk.Wq^T over d, [h'][h]
__device__ __half g_t[16384LL * 1024];        // T = x.W''  ([s][h'])
__device__ __half g_vt[8LL * 1024 * 2048];
__device__ float  g_scores[8LL * 2048 * 2048];
__device__ __half g_ah[8LL * 2048 * 2048];

// ---------------- PTX helpers ----------------
__device__ __forceinline__ uint32_t s2u(const void* p) {
    uint32_t a;
    asm("{ .reg .u64 t; cvta.to.shared.u64 t, %1; cvt.u32.u64 %0, t; }" : "=r"(a) : "l"(p));
    return a;
}
__device__ __forceinline__ void cpasync16(uint32_t d, const void* s) {
    asm volatile("cp.async.cg.shared.global [%0], [%1], 16;" :: "r"(d), "l"(s) : "memory");
}
#define CP_COMMIT() asm volatile("cp.async.commit_group;" ::: "memory")
#define CP_WAIT(n)  asm volatile("cp.async.wait_group %0;" :: "n"(n) : "memory")

__device__ __forceinline__ void ldsm4(uint32_t* r, uint32_t a) {
    asm volatile("ldmatrix.sync.aligned.m8n8.x4.shared.b16 {%0,%1,%2,%3}, [%4];"
                 : "=r"(r[0]), "=r"(r[1]), "=r"(r[2]), "=r"(r[3]) : "r"(a));
}
__device__ __forceinline__ void mma_f16(float* d, const uint32_t* a, const uint32_t* b) {
    asm volatile(
        "mma.sync.aligned.m16n8k16.row.col.f32.f16.f16.f32 "
        "{%0,%1,%2,%3}, {%4,%5,%6,%7}, {%8,%9}, {%0,%1,%2,%3};"
        : "+f"(d[0]), "+f"(d[1]), "+f"(d[2]), "+f"(d[3])
        : "r"(a[0]), "r"(a[1]), "r"(a[2]), "r"(a[3]), "r"(b[0]), "r"(b[1]));
}

// ---------------- fp16 GEMM: C[M,N] = sum_k A[m][k]*B[n][k] ----------------
template <int OUT>   // 0: fp32 C, 1: fp16 C
__global__ __launch_bounds__(512, 1) void h_gemm(
    const __half* __restrict__ Ag, const __half* __restrict__ Bg,
    float* __restrict__ Cf, __half* __restrict__ Ch,
    int K, int lda, int ldb, int ldc,
    long long batA, long long batB, long long batC)
{
    extern __shared__ char smem[];
    const uint32_t sb = s2u(smem);
    const int tid = threadIdx.x;
    const int lane = tid & 31, warp = tid >> 5;
    const int wM = warp & 1;        // 2 warps along M (64 rows each)
    const int wN = warp >> 1;       // 8 warps along N (32 cols each)
    const int lm = lane >> 3, lr = lane & 7;
    const int gid = lane >> 2, tig = lane & 3;

    const long long rowBase = (long long)blockIdx.y * BMT;
    const long long colBase = (long long)blockIdx.x * BNT;
    const char* A = (const char*)(Ag + blockIdx.z * batA);
    const char* B = (const char*)(Bg + blockIdx.z * batB);

    const uint32_t aBase = (uint32_t)(wM * 64 + (lm & 1) * 8 + lr) * SSTR + ((lm >> 1) * 8) * 2;
    const uint32_t bBase = TILE_A + (uint32_t)(wN * 32 + (lm >> 1) * 8 + lr) * SSTR + ((lm & 1) * 8) * 2;

    const int ldrA = tid >> 2;           // A row 0..127
    const int cbA  = (tid & 3) * 32;     // 0/32/64/96 within 128B row
    const int ldrB = tid >> 1;           // B row 0..255
    const int cbB  = (tid & 1) * 64;     // 0/64 within 128B row

    float acc[4][4][4];
#pragma unroll
    for (int i = 0; i < 4; i++)
#pragma unroll
        for (int j = 0; j < 4; j++)
#pragma unroll
            for (int c = 0; c < 4; c++) acc[i][j][c] = 0.f;

    const int nCh = K / BKT;

    auto loadA = [&](int c) {
        const uint32_t st = sb + (uint32_t)(c % 3) * STAGE_B;
        const char* g = A + (rowBase + ldrA) * (long long)lda * 2 + (long long)c * (BKT * 2) + cbA;
        const uint32_t t0 = st + ldrA * SSTR + cbA;
        cpasync16(t0, g);
        cpasync16(t0 + 16, g + 16);
    };
    auto loadB = [&](int c) {
        const uint32_t st = sb + (uint32_t)(c % 3) * STAGE_B + TILE_A;
        const char* g = B + (colBase + ldrB) * (long long)ldb * 2 + (long long)c * (BKT * 2) + cbB;
        const uint32_t t0 = st + ldrB * SSTR + cbB;
#pragma unroll
        for (int i = 0; i < 4; i++)
            cpasync16(t0 + i * 16, g + i * 16);
    };

    loadA(0); loadB(0); CP_COMMIT();
    loadA(1); loadB(1); CP_COMMIT();

    for (int c = 0; c < nCh; ++c) {
        if (c + 1 < nCh) { CP_WAIT(1); } else { CP_WAIT(0); }
        __syncthreads();   // stage c visible (landed a chunk ago); safe to refill (c+2)%3

        const uint32_t stg = sb + (uint32_t)(c % 3) * STAGE_B;
        const bool pf = (c + 2 < nCh);

#pragma unroll
        for (int i = 0; i < 4; i++) {           // ks = i*16
            uint32_t af[4][4], bf_[2][4];
            const uint32_t ko = (uint32_t)i * 32;
#pragma unroll
            for (int mt = 0; mt < 4; mt++)
                ldsm4(af[mt], stg + aBase + mt * 16 * SSTR + ko);
#pragma unroll
            for (int p = 0; p < 2; p++)
                ldsm4(bf_[p], stg + bBase + p * 16 * SSTR + ko);

            if (i == 0 && pf) loadA(c + 2);     // prefetch hides under MMAs
            if (i == 1 && pf) { loadB(c + 2); CP_COMMIT(); }

#pragma unroll
            for (int mt = 0; mt < 4; mt++)
#pragma unroll
                for (int nt = 0; nt < 4; nt++)
                    mma_f16(acc[mt][nt], af[mt], &bf_[nt >> 1][(nt & 1) * 2]);
        }
    }

    // ---- epilogue ----
#pragma unroll
    for (int mt = 0; mt < 4; mt++) {
        const long long r0 = rowBase + wM * 64 + mt * 16 + gid;
#pragma unroll
        for (int nt = 0; nt < 4; nt++) {
            const long long c0 = colBase + wN * 32 + nt * 8 + tig * 2;
            if (OUT == 1) {
                __half* cp = Ch + blockIdx.z * batC;
                *(__half2*)&cp[r0 * ldc + c0] =
                    __floats2half2_rn(acc[mt][nt][0], acc[mt][nt][1]);
                *(__half2*)&cp[(r0 + 8) * ldc + c0] =
                    __floats2half2_rn(acc[mt][nt][2], acc[mt][nt][3]);
            } else {
                float* cp = Cf + blockIdx.z * batC;
                *(float2*)&cp[r0 * ldc + c0] =
                    make_float2(acc[mt][nt][0], acc[mt][nt][1]);
                *(float2*)&cp[(r0 + 8) * ldc + c0] =
                    make_float2(acc[mt][nt][2], acc[mt][nt][3]);
            }
        }
    }
}

// ---------------- conversion kernels ----------------
__global__ __launch_bounds__(256) void cvt_f2h(
    const float4* __restrict__ in, __half* __restrict__ out, int n4)
{
    int i = blockIdx.x * 256 + threadIdx.x;
    if (i >= n4) return;
    float4 v = in[i];
    ((__half2*)out)[2 * i]     = __floats2half2_rn(v.x, v.y);
    ((__half2*)out)[2 * i + 1] = __floats2half2_rn(v.z, v.w);
}

// out[z][c][r] = in[z][r][c] as fp16
__global__ __launch_bounds__(256) void transpose_cvt(
    const float* __restrict__ in, __half* __restrict__ out,
    int R, int C, long long batIn, long long batOut)
{
    __shared__ float t[32][33];
    const float* ip = in + blockIdx.z * batIn;
    const long long ob = blockIdx.z * batOut;
    const int c0 = blockIdx.x * 32, r0 = blockIdx.y * 32;
    const int tx = threadIdx.x, ty = threadIdx.y;
#pragma unroll
    for (int i = 0; i < 32; i += 8)
        t[ty + i][tx] = ip[(long long)(r0 + ty + i) * C + c0 + tx];
    __syncthreads();
#pragma unroll
    for (int i = 0; i < 32; i += 8)
        out[ob + (long long)(c0 + ty + i) * R + r0 + tx] = __float2half(t[tx][ty + i]);
}

// softmax over rows of 2048; 1/8 scale folded in; fp16 output
__global__ __launch_bounds__(256) void softmax_h(
    const float* __restrict__ sc, __half* __restrict__ out)
{
    const float SC = 0.125f;
    const long long row = blockIdx.x;
    const float* p = sc + row * 2048;
    const int t = threadIdx.x, lane = t & 31, w = t >> 5;

    float4 v0 = ((const float4*)p)[t];
    float4 v1 = ((const float4*)p)[t + 256];
    float x[8] = {v0.x, v0.y, v0.z, v0.w, v1.x, v1.y, v1.z, v1.w};

    float m = -1e30f;
#pragma unroll
    for (int i = 0; i < 8; i++) { x[i] *= SC; m = fmaxf(m, x[i]); }
#pragma unroll
    for (int o = 16; o > 0; o >>= 1) m = fmaxf(m, __shfl_xor_sync(0xffffffffu, m, o));

    __shared__ float red[8];
    if (lane == 0) red[w] = m;
    __syncthreads();
    float bm = red[0];
#pragma unroll
    for (int i = 1; i < 8; i++) bm = fmaxf(bm, red[i]);

    float s = 0.f;
#pragma unroll
    for (int i = 0; i < 8; i++) { x[i] = expf(x[i] - bm); s += x[i]; }
#pragma unroll
    for (int o = 16; o > 0; o >>= 1) s += __shfl_xor_sync(0xffffffffu, s, o);
    __syncthreads();
    if (lane == 0) red[w] = s;
    __syncthreads();
    float tot = 0.f;
#pragma unroll
    for (int i = 0; i < 8; i++) tot += red[i];
    const float inv = 1.0f / tot;

    __half2* op = (__half2*)(out + row * 2048);
    op[2 * t]       = __floats2half2_rn(x[0] * inv, x[1] * inv);
    op[2 * t + 1]   = __floats2half2_rn(x[2] * inv, x[3] * inv);
    op[2 * t + 512] = __floats2half2_rn(x[4] * inv, x[5] * inv);
    op[2 * t + 513] = __floats2half2_rn(x[6] * inv, x[7] * inv);
}

// ---------------- host ----------------
extern "C" void kernel_launch(void* const* d_in, const int* in_sizes, int n_in,
                              void* d_out, int out_size) {
    const float* x = (const float*)d_in[0];
    const float* w = (const float*)d_in[1];
    float* out = (float*)d_out;

    __half *xh, *wh, *wtv, *wpt, *th, *vt, *ah;
    float* scores;
    cudaGetSymbolAddress((void**)&xh, g_xh);
    cudaGetSymbolAddress((void**)&wh, g_wh);
    cudaGetSymbolAddress((void**)&wtv, g_wtv);
    cudaGetSymbolAddress((void**)&wpt, g_wpt);
    cudaGetSymbolAddress((void**)&th, g_t);
    cudaGetSymbolAddress((void**)&vt, g_vt);
    cudaGetSymbolAddress((void**)&scores, g_scores);
    cudaGetSymbolAddress((void**)&ah, g_ah);

    cudaFuncSetAttribute(h_gemm<0>, cudaFuncAttributeMaxDynamicSharedMemorySize, SMEM_SZ);
    cudaFuncSetAttribute(h_gemm<1>, cudaFuncAttributeMaxDynamicSharedMemorySize, SMEM_SZ);

    // one-time stream/event setup (resources, not work; work per call is identical)
    static bool inited = false;
    static cudaStream_t s1, s2;
    static cudaEvent_t evRoot, evXh, evWtv, evWpt, evVt;
    if (!inited) {
        cudaStreamCreateWithFlags(&s1, cudaStreamNonBlocking);
        cudaStreamCreateWithFlags(&s2, cudaStreamNonBlocking);
        cudaEventCreateWithFlags(&evRoot, cudaEventDisableTiming);
        cudaEventCreateWithFlags(&evXh,   cudaEventDisableTiming);
        cudaEventCreateWithFlags(&evWtv,  cudaEventDisableTiming);
        cudaEventCreateWithFlags(&evWpt,  cudaEventDisableTiming);
        cudaEventCreateWithFlags(&evVt,   cudaEventDisableTiming);
        inited = true;
    }

    // ---- fork side streams off the (capturing) default stream ----
    cudaEventRecord(evRoot, 0);
    cudaStreamWaitEvent(s1, evRoot, 0);
    cudaStreamWaitEvent(s2, evRoot, 0);

    // s0: x -> fp16
    cvt_f2h<<<16384, 256>>>((const float4*)x, xh, 16384 * 1024 / 4);
    cudaEventRecord(evXh, 0);

    // s1: weight path: Wq,Wk fp16; Wv^T; W''
    cvt_f2h<<<2048, 256, 0, s1>>>((const float4*)w, wh, 2 * 1024 * 1024 / 4);
    transpose_cvt<<<dim3(32, 32, 1), dim3(32, 8), 0, s1>>>(
        w + 2LL * 1024 * 1024, wtv, 1024, 1024, 0LL, 0LL);
    cudaEventRecord(evWtv, s1);
    h_gemm<1><<<dim3(4, 8, 1), 512, SMEM_SZ, s1>>>(
        wh + 1024LL * 1024, wh, nullptr, wpt,
        1024, 1024, 1024, 1024, 0LL, 0LL, 0LL);
    cudaEventRecord(evWpt, s1);

    // s2: V projection (needs xh + wtv); overlaps T and S on s0
    cudaStreamWaitEvent(s2, evXh, 0);
    cudaStreamWaitEvent(s2, evWtv, 0);
    h_gemm<1><<<dim3(8, 8, 8), 512, SMEM_SZ, s2>>>(
        wtv, xh, nullptr, vt,
        1024, 1024, 1024, 2048, 0LL, 2048LL * 1024, 1024LL * 2048);
    cudaEventRecord(evVt, s2);

    // s0: T = x . W''  (needs wpt from s1)
    cudaStreamWaitEvent(0, evWpt, 0);
    h_gemm<1><<<dim3(4, 128, 1), 512, SMEM_SZ>>>(
        xh, wpt, nullptr, th,
        1024, 1024, 1024, 1024, 0LL, 0LL, 0LL);

    // s0: S = T . x^T per batch
    h_gemm<0><<<dim3(8, 16, 8), 512, SMEM_SZ>>>(
        th, xh, scores, nullptr,
        1024, 1024, 1024, 2048, 2048LL * 1024, 2048LL * 1024, 2048LL * 2048);

    // s0: softmax -> fp16 A
    softmax_h<<<16384, 256>>>(scores, ah);

    // join: V must be done before AV
    cudaStreamWaitEvent(0, evVt, 0);

    // s0: out = A @ V per batch
    h_gemm<0><<<dim3(4, 16, 8), 512, SMEM_SZ>>>(
        ah, vt, out, nullptr,
        2048, 2048, 2048, 1024, 2048LL * 2048, 1024LL * 2048, 2048LL * 1024);
}